// round 7
// baseline (speedup 1.0000x reference)
#include <cuda_runtime.h>

// Fused: ConvTranspose3d(3->16, k=3, s=2, p=1, out_pad=1) + bias + MaxPool3d(2)
//        + softmax(ch) - subtract, swish, max(ch).
// x: [4,3,64,64,64] f32, w: [3,16,3,3,3], b: [16], subtract: [16] -> out [4,64,64,64]
//
// Lane c=lane&15 owns channel c; half=lane>>4 owns one of 2 adjacent-w voxels.
// R7: weights moved registers -> smem (27 float4 (kd,kh)-triples per channel,
// one LDS.128 feeds 12 FMAs), comb-outer loop. Frees ~81 regs/lane ->
// __launch_bounds__(128,6) -> 24 warps/SM instead of 16. Parity-split float4
// x tile (R5) and no-max-pass softmax epilogue retained.

#define N_BATCH 4
#define CIN 3
#define COUT 16
#define DIM 64

// pair decode: 9 (kd,kh) pairs per cin, grouped by comb type (dd,hh):
//  t0 (0,0): (1,1)(1,2)(2,1)(2,2)   idx 0..3
//  t1 (0,1): (1,0)(2,0)             idx 4..5
//  t2 (1,0): (0,1)(0,2)             idx 6..7
//  t3 (1,1): (0,0)                  idx 8
__device__ const int g_kd_of[9] = {1, 1, 2, 2, 1, 2, 0, 0, 0};
__device__ const int g_kh_of[9] = {1, 2, 1, 2, 0, 0, 1, 2, 0};

__global__ __launch_bounds__(128, 6) void fused_ctmp_softswish_kernel(
    const float* __restrict__ x,
    const float* __restrict__ wgt,
    const float* __restrict__ bias_g,
    const float* __restrict__ sub_g,
    float* __restrict__ out)
{
    // x tile: tile[warp][comb][p][q] = {x_row[4q+p], +1, +2, +3}
    __shared__ float4 tile[4][12][2][16];
    // weights: wsm4[c*27 + cin*9 + pair] = {w[kw=0], w[kw=1], w[kw=2], 0}
    __shared__ float4 wsm4[16 * 27];

    const int tid  = threadIdx.x;
    const int lane = tid & 31;
    const int wid  = tid >> 5;
    const int c    = lane & 15;
    const int half = lane >> 4;

    // ---- one-time: pack weights into smem ----
    for (int idx = tid; idx < 16 * 27; idx += 128) {
        const int cc  = idx & 15;
        const int p   = idx >> 4;        // 0..26
        const int cin = p / 9;
        const int r   = p % 9;
        const int kd  = g_kd_of[r];
        const int kh  = g_kh_of[r];
        const int gb  = (((cin * COUT + cc) * 3 + kd) * 3 + kh) * 3;
        wsm4[cc * 27 + p] = make_float4(__ldg(&wgt[gb + 0]),
                                        __ldg(&wgt[gb + 1]),
                                        __ldg(&wgt[gb + 2]), 0.f);
    }
    __syncthreads();

    const float bias = __ldg(&bias_g[c]);
    const float subc = __ldg(&sub_g[c]);
    const float4* wrow = &wsm4[c * 27];

    const int gwarp  = blockIdx.x * 4 + wid;
    const int nwarps = gridDim.x * 4;
    const int nrows  = N_BATCH * DIM * DIM;

    const int bp = lane >> 4;
    const int bq = lane & 15;

    // per comb type: number of (kd,kh) pairs and offset within the cin group
    const int PCNT[4] = {4, 2, 2, 1};
    const int POFF[4] = {0, 4, 6, 8};

    for (int row = gwarp; row < nrows; row += nwarps) {
        const int h = row & 63;
        const int d = (row >> 6) & 63;
        const int n = row >> 12;

        // ---- build parity-split float4 x tile ----
        #pragma unroll
        for (int comb = 0; comb < 12; ++comb) {
            const int cin = comb >> 2;
            const int dd  = (comb >> 1) & 1;
            const int hh  = comb & 1;
            const int dcur = d + dd;
            const int hcur = h + hh;
            const bool rowok = (dcur < DIM) && (hcur < DIM);
            const float* src = x + (((n * CIN + cin) * DIM + dcur) * DIM + hcur) * DIM;
            const int base = 4 * bq + bp;
            float a0 = 0.f, a1 = 0.f, a2 = 0.f, a3 = 0.f;
            if (rowok) {
                a0 = __ldg(&src[base]);
                a1 = __ldg(&src[base + 1]);
                a2 = __ldg(&src[base + 2]);
                if (base + 3 < DIM) a3 = __ldg(&src[base + 3]);
            }
            tile[wid][comb][bp][bq] = make_float4(a0, a1, a2, a3);
        }
        __syncwarp();

        float* orow = out + ((n * DIM + d) * DIM + h) * DIM;

        for (int w0 = 0; w0 < DIM; w0 += 8) {
            const int q0 = w0 >> 2;

            // acc[jp*2+jj][pd*4+ph*2+pw]
            float acc[4][8];
            #pragma unroll
            for (int j = 0; j < 4; ++j)
                #pragma unroll
                for (int i = 0; i < 8; ++i) acc[j][i] = 0.f;

            #pragma unroll
            for (int comb = 0; comb < 12; ++comb) {
                const int cin = comb >> 2;
                const int t   = comb & 3;      // dd*2+hh
                const int np  = PCNT[t];
                const int po  = POFF[t];

                // load this comb's weight triples (1..4 LDS.128)
                float4 wq[4];
                #pragma unroll
                for (int i = 0; i < 4; ++i)
                    if (i < np) wq[i] = wrow[cin * 9 + po + i];

                #pragma unroll
                for (int jp = 0; jp < 2; ++jp) {
                    const float4 v = tile[wid][comb][half][q0 + jp];
                    const float xjj0[2] = {v.x, v.z};
                    const float xjj1[2] = {v.y, v.w};

                    #pragma unroll
                    for (int i = 0; i < 4; ++i) {
                        if (i >= np) continue;
                        // (pd,ph) per comb type / pair index
                        const int pd = (t == 0) ? (i >> 1) : (t == 1) ? i : 1;
                        const int ph = (t == 0) ? (i & 1)  : (t == 2) ? i : 1;
                        const int a0i = pd * 4 + ph * 2;       // pw=0
                        const int a1i = a0i + 1;               // pw=1
                        #pragma unroll
                        for (int jj = 0; jj < 2; ++jj) {
                            float* a = acc[jp * 2 + jj];
                            a[a0i] = fmaf(wq[i].y, xjj0[jj], a[a0i]);
                            a[a1i] = fmaf(wq[i].z, xjj0[jj], a[a1i]);
                            a[a1i] = fmaf(wq[i].x, xjj1[jj], a[a1i]);
                        }
                    }
                }
            }

            // ---- maxpool over 8 candidates + bias ----
            float m[4];
            #pragma unroll
            for (int j = 0; j < 4; ++j) {
                const float* a = acc[j];
                float mm = fmaxf(fmaxf(fmaxf(a[0], a[1]), fmaxf(a[2], a[3])),
                                 fmaxf(fmaxf(a[4], a[5]), fmaxf(a[6], a[7])));
                m[j] = mm + bias;
            }

            // ---- epilogue: no softmax max-pass; 2 chains interleaved (ILP=4) ----
            float e[4], sum[4];
            #pragma unroll
            for (int j = 0; j < 4; ++j) { e[j] = __expf(m[j]); sum[j] = e[j]; }
            #pragma unroll
            for (int s = 1; s < 16; s <<= 1) {
                #pragma unroll
                for (int j = 0; j < 4; ++j)
                    sum[j] += __shfl_xor_sync(0xffffffffu, sum[j], s);
            }

            float r[4];
            #pragma unroll
            for (int j = 0; j < 4; ++j) {
                const float sft = __fdividef(e[j], sum[j]);
                const float z   = sft - subc;
                r[j] = __fdividef(z, 1.f + __expf(-z));   // swish
            }
            #pragma unroll
            for (int s = 1; s < 16; s <<= 1) {
                #pragma unroll
                for (int j = 0; j < 4; ++j)
                    r[j] = fmaxf(r[j], __shfl_xor_sync(0xffffffffu, r[j], s));
            }

            if (c == 0) {
                #pragma unroll
                for (int j = 0; j < 4; ++j)
                    orow[w0 + 2 * j + half] = r[j];
            }
        }
        __syncwarp();
    }
}

extern "C" void kernel_launch(void* const* d_in, const int* in_sizes, int n_in,
                              void* d_out, int out_size) {
    const float* x   = (const float*)d_in[0];
    const float* w   = (const float*)d_in[1];
    const float* b   = (const float*)d_in[2];
    const float* sub = (const float*)d_in[3];
    float* out = (float*)d_out;
    (void)in_sizes; (void)n_in; (void)out_size;
    fused_ctmp_softswish_kernel<<<2048, 128>>>(x, w, b, sub, out);
}

// round 9
// speedup vs baseline: 1.3230x; 1.3230x over previous
#include <cuda_runtime.h>

// Fused: ConvTranspose3d(3->16, k=3, s=2, p=1, out_pad=1) + bias + MaxPool3d(2)
//        + softmax(ch) - subtract, swish, max(ch).
// x: [4,3,64,64,64] f32, w: [3,16,3,3,3], b: [16], subtract: [16] -> out [4,64,64,64]
//
// Lane c=lane&15 owns channel c; half=lane>>4 owns one of 2 adjacent-w voxels.
// R9: R8 with the weight-table init bug fixed (strided loop covers all 144
// entries with a 128-thread block). cin2's 27 weights stream from conflict-free
// smem; cin0/cin1 weights (54) in registers; __launch_bounds__(128,5).

#define N_BATCH 4
#define CIN 3
#define COUT 16
#define DIM 64

// cin2 pair list grouped by comb type t = dd*2+hh:
//  t0 (dd0,hh0): (kd,kh) = (1,1)(1,2)(2,1)(2,2)  -> pairs 0..3
//  t1 (dd0,hh1): (1,0)(2,0)                       -> pairs 4..5
//  t2 (dd1,hh0): (0,1)(0,2)                       -> pairs 6..7
//  t3 (dd1,hh1): (0,0)                            -> pair  8
__device__ const int g_kd_of[9] = {1, 1, 2, 2, 1, 2, 0, 0, 0};
__device__ const int g_kh_of[9] = {1, 2, 1, 2, 0, 0, 1, 2, 0};

__global__ __launch_bounds__(128, 5) void fused_ctmp_softswish_kernel(
    const float* __restrict__ x,
    const float* __restrict__ wgt,
    const float* __restrict__ bias_g,
    const float* __restrict__ sub_g,
    float* __restrict__ out)
{
    // x tile: tile[warp][comb][p][q] = {x_row[4q+p], +1, +2, +3}
    __shared__ float4 tile[4][12][2][16];
    // cin2 weights: wc2sm[pair][channel] = {w[kw=0], w[kw=1], w[kw=2], 0}
    __shared__ float4 wc2sm[9][16];

    const int tid  = threadIdx.x;
    const int lane = tid & 31;
    const int wid  = tid >> 5;
    const int c    = lane & 15;
    const int half = lane >> 4;

    // ---- one-time: pack cin2 weights into smem (channel-contiguous) ----
    for (int idx = tid; idx < 144; idx += 128) {
        const int p  = idx >> 4;   // pair 0..8
        const int cc = idx & 15;   // channel
        const int kd = g_kd_of[p];
        const int kh = g_kh_of[p];
        const int gb = (((2 * COUT + cc) * 3 + kd) * 3 + kh) * 3;
        wc2sm[p][cc] = make_float4(__ldg(&wgt[gb + 0]),
                                   __ldg(&wgt[gb + 1]),
                                   __ldg(&wgt[gb + 2]), 0.f);
    }

    // ---- cin0/cin1 weights (54 floats) in registers ----
    float wr[54];
    #pragma unroll
    for (int cin = 0; cin < 2; ++cin) {
        #pragma unroll
        for (int k = 0; k < 27; ++k)
            wr[cin * 27 + k] = __ldg(&wgt[(cin * COUT + c) * 27 + k]);
    }
    const float bias = __ldg(&bias_g[c]);
    const float subc = __ldg(&sub_g[c]);
    __syncthreads();

    // parity tap tables (cin0/1 path): even pos -> k=1 @ off0; odd -> k=2 @ off0, k=0 @ off1
    const int NP[2]      = {1, 2};
    const int KTAP[2][2] = {{1, 0}, {2, 0}};
    const int XOFF[2][2] = {{0, 0}, {0, 1}};
    // cin2 comb-type tables
    const int PCNT[4] = {4, 2, 2, 1};
    const int POFF[4] = {0, 4, 6, 8};

    const int gwarp  = blockIdx.x * 4 + wid;
    const int nwarps = gridDim.x * 4;
    const int nrows  = N_BATCH * DIM * DIM;

    const int bp = lane >> 4;
    const int bq = lane & 15;

    for (int row = gwarp; row < nrows; row += nwarps) {
        const int h = row & 63;
        const int d = (row >> 6) & 63;
        const int n = row >> 12;

        // ---- build parity-split float4 x tile ----
        #pragma unroll
        for (int comb = 0; comb < 12; ++comb) {
            const int cin = comb >> 2;
            const int dd  = (comb >> 1) & 1;
            const int hh  = comb & 1;
            const int dcur = d + dd;
            const int hcur = h + hh;
            const bool rowok = (dcur < DIM) && (hcur < DIM);
            const float* src = x + (((n * CIN + cin) * DIM + dcur) * DIM + hcur) * DIM;
            const int base = 4 * bq + bp;
            float a0 = 0.f, a1 = 0.f, a2 = 0.f, a3 = 0.f;
            if (rowok) {
                a0 = __ldg(&src[base]);
                a1 = __ldg(&src[base + 1]);
                a2 = __ldg(&src[base + 2]);
                if (base + 3 < DIM) a3 = __ldg(&src[base + 3]);
            }
            tile[wid][comb][bp][bq] = make_float4(a0, a1, a2, a3);
        }
        __syncwarp();

        float* orow = out + ((n * DIM + d) * DIM + h) * DIM;

        for (int w0 = 0; w0 < DIM; w0 += 8) {
            const int q0 = w0 >> 2;
            float m[4];

            #pragma unroll
            for (int jp = 0; jp < 2; ++jp) {
                float acc[2][8];
                #pragma unroll
                for (int jj = 0; jj < 2; ++jj)
                    #pragma unroll
                    for (int i = 0; i < 8; ++i) acc[jj][i] = 0.f;

                // ---- cin0/cin1: register weights (R5 path) ----
                #pragma unroll
                for (int comb = 0; comb < 8; ++comb) {
                    const int cin = comb >> 2;
                    const int dd  = (comb >> 1) & 1;
                    const int hh  = comb & 1;
                    const float4 v = tile[wid][comb][half][q0 + jp];
                    const float xxs[2][2] = {{v.x, v.y}, {v.z, v.w}};

                    #pragma unroll
                    for (int pd = 0; pd < 2; ++pd) {
                        #pragma unroll
                        for (int jd = 0; jd < 2; ++jd) {
                            if (jd >= NP[pd] || XOFF[pd][jd] != dd) continue;
                            const int kd = KTAP[pd][jd];
                            #pragma unroll
                            for (int ph = 0; ph < 2; ++ph) {
                                #pragma unroll
                                for (int jh = 0; jh < 2; ++jh) {
                                    if (jh >= NP[ph] || XOFF[ph][jh] != hh) continue;
                                    const int kh = KTAP[ph][jh];
                                    #pragma unroll
                                    for (int pw = 0; pw < 2; ++pw) {
                                        #pragma unroll
                                        for (int jw = 0; jw < 2; ++jw) {
                                            if (jw >= NP[pw]) continue;
                                            const int kw = KTAP[pw][jw];
                                            const float wv_ = wr[cin * 27 + kd * 9 + kh * 3 + kw];
                                            const int ww = XOFF[pw][jw];
                                            #pragma unroll
                                            for (int jj = 0; jj < 2; ++jj)
                                                acc[jj][pd * 4 + ph * 2 + pw] =
                                                    fmaf(wv_, xxs[jj][ww], acc[jj][pd * 4 + ph * 2 + pw]);
                                        }
                                    }
                                }
                            }
                        }
                    }
                }

                // ---- cin2: weights streamed from smem (triples) ----
                #pragma unroll
                for (int comb = 8; comb < 12; ++comb) {
                    const int t  = comb & 3;
                    const int np = PCNT[t];
                    const int po = POFF[t];
                    const float4 v = tile[wid][comb][half][q0 + jp];
                    const float xjj0[2] = {v.x, v.z};   // x[wv] for jj=0,1
                    const float xjj1[2] = {v.y, v.w};   // x[wv+1]

                    #pragma unroll
                    for (int i = 0; i < 4; ++i) {
                        if (i >= np) continue;
                        const float4 wq = wc2sm[po + i][c];
                        const int pd = (t == 0) ? (i >> 1) : (t == 1) ? i : 1;
                        const int ph = (t == 0) ? (i & 1)  : (t == 2) ? i : 1;
                        const int a0i = pd * 4 + ph * 2;   // pw=0
                        const int a1i = a0i + 1;           // pw=1
                        #pragma unroll
                        for (int jj = 0; jj < 2; ++jj) {
                            float* a = acc[jj];
                            a[a0i] = fmaf(wq.y, xjj0[jj], a[a0i]);
                            a[a1i] = fmaf(wq.z, xjj0[jj], a[a1i]);
                            a[a1i] = fmaf(wq.x, xjj1[jj], a[a1i]);
                        }
                    }
                }

                #pragma unroll
                for (int jj = 0; jj < 2; ++jj) {
                    const float* a = acc[jj];
                    float mm = fmaxf(fmaxf(fmaxf(a[0], a[1]), fmaxf(a[2], a[3])),
                                     fmaxf(fmaxf(a[4], a[5]), fmaxf(a[6], a[7])));
                    m[2 * jp + jj] = mm + bias;
                }
            }

            // ---- epilogue: no softmax max-pass; 2 chains interleaved (ILP=4) ----
            float e[4], sum[4];
            #pragma unroll
            for (int j = 0; j < 4; ++j) { e[j] = __expf(m[j]); sum[j] = e[j]; }
            #pragma unroll
            for (int s = 1; s < 16; s <<= 1) {
                #pragma unroll
                for (int j = 0; j < 4; ++j)
                    sum[j] += __shfl_xor_sync(0xffffffffu, sum[j], s);
            }

            float r[4];
            #pragma unroll
            for (int j = 0; j < 4; ++j) {
                const float sft = __fdividef(e[j], sum[j]);
                const float z   = sft - subc;
                r[j] = __fdividef(z, 1.f + __expf(-z));   // swish
            }
            #pragma unroll
            for (int s = 1; s < 16; s <<= 1) {
                #pragma unroll
                for (int j = 0; j < 4; ++j)
                    r[j] = fmaxf(r[j], __shfl_xor_sync(0xffffffffu, r[j], s));
            }

            if (c == 0) {
                #pragma unroll
                for (int j = 0; j < 4; ++j)
                    orow[w0 + 2 * j + half] = r[j];
            }
        }
        __syncwarp();
    }
}

extern "C" void kernel_launch(void* const* d_in, const int* in_sizes, int n_in,
                              void* d_out, int out_size) {
    const float* x   = (const float*)d_in[0];
    const float* w   = (const float*)d_in[1];
    const float* b   = (const float*)d_in[2];
    const float* sub = (const float*)d_in[3];
    float* out = (float*)d_out;
    (void)in_sizes; (void)n_in; (void)out_size;
    fused_ctmp_softswish_kernel<<<2048, 128>>>(x, w, b, sub, out);
}